// round 8
// baseline (speedup 1.0000x reference)
#include <cuda_runtime.h>
#include <cuda_bf16.h>

#define G 256
#define D 128
#define WARP_FULL 0xffffffffu

// Scratch accumulators (allocation-free rule: __device__ globals)
__device__ float g_sums[G * D];
__device__ float g_counts[G];

// ---------------------------------------------------------------------------
// Kernel 0: zero the accumulators (graph replays re-use them)
// ---------------------------------------------------------------------------
__global__ void zero_kernel() {
    int i = blockIdx.x * blockDim.x + threadIdx.x;
    if (i < G * D) g_sums[i] = 0.0f;
    if (i < G)     g_counts[i] = 0.0f;
}

// ---------------------------------------------------------------------------
// Kernel 1: streaming segment-sum.
// Each warp owns a contiguous chunk of rows. Lane L accumulates columns
// [4L, 4L+4) in a float4 register. batch is sorted, so we flush to global
// atomics only when the graph id changes (rare: ~G + #warps flushes total).
// Fast path: 32 rows at a time with a cooperative batch load + uniformity
// ballot -> fully unrolled 32 independent float4 loads (high MLP).
// ---------------------------------------------------------------------------
__device__ __forceinline__ void flush_seg(int g, int lane, const float4& acc, float cnt) {
    if (g < 0 || g >= G || cnt == 0.0f) return;   // clamp: never index OOB
    float* s = &g_sums[g * D + lane * 4];
    atomicAdd(s + 0, acc.x);
    atomicAdd(s + 1, acc.y);
    atomicAdd(s + 2, acc.z);
    atomicAdd(s + 3, acc.w);
    if (lane == 0) atomicAdd(&g_counts[g], cnt);
}

__global__ __launch_bounds__(256) void reduce_kernel(
    const float4* __restrict__ x4,      // [N, 32] float4 view of x[N,128]
    const int* __restrict__ batch,      // [N] int32
    int N, int rows_per_warp)
{
    const int warp_global = (blockIdx.x * blockDim.x + threadIdx.x) >> 5;
    const int lane = threadIdx.x & 31;

    int r0 = warp_global * rows_per_warp;
    if (r0 >= N) return;
    int r1 = min(N, r0 + rows_per_warp);

    float4 acc = make_float4(0.f, 0.f, 0.f, 0.f);
    float  cnt = 0.0f;
    int    cur_g = -1;

    int r = r0;
    while (r < r1) {
        int m = min(32, r1 - r);
        // cooperative batch load (inactive lanes replicate row r's value)
        int bi = batch[(lane < m) ? (r + lane) : r];
        int b0 = __shfl_sync(WARP_FULL, bi, 0);
        bool uni = __all_sync(WARP_FULL, bi == b0);

        if (uni && m == 32) {
            if (b0 != cur_g) {
                flush_seg(cur_g, lane, acc, cnt);
                acc = make_float4(0.f, 0.f, 0.f, 0.f);
                cnt = 0.0f;
                cur_g = b0;
            }
            const float4* p = x4 + (size_t)r * 32 + lane;
            #pragma unroll
            for (int i = 0; i < 32; ++i) {
                float4 v = p[(size_t)i * 32];
                acc.x += v.x; acc.y += v.y; acc.z += v.z; acc.w += v.w;
            }
            cnt += 32.0f;
            r += 32;
        } else {
            // slow path: per-row (segment boundary inside the 32-block, or tail)
            for (int i = 0; i < m; ++i) {
                int gi = __shfl_sync(WARP_FULL, bi, i);
                if (gi != cur_g) {
                    flush_seg(cur_g, lane, acc, cnt);
                    acc = make_float4(0.f, 0.f, 0.f, 0.f);
                    cnt = 0.0f;
                    cur_g = gi;
                }
                float4 v = x4[(size_t)(r + i) * 32 + lane];
                acc.x += v.x; acc.y += v.y; acc.z += v.z; acc.w += v.w;
                cnt += 1.0f;
            }
            r += m;
        }
    }
    flush_seg(cur_g, lane, acc, cnt);
}

// ---------------------------------------------------------------------------
// Kernel 2: per-graph mean + MLP head.
// 256 blocks (one per graph) x 64 threads (one per hidden unit).
// ---------------------------------------------------------------------------
__global__ __launch_bounds__(64) void mlp_kernel(
    const float* __restrict__ W1,   // [128, 64] row-major
    const float* __restrict__ b1,   // [64]
    const float* __restrict__ W2,   // [64, 1]
    const float* __restrict__ b2,   // [1]
    float* __restrict__ out)        // [G, 1]
{
    const int g = blockIdx.x;
    const int j = threadIdx.x;   // hidden unit 0..63

    __shared__ float mean[D];
    __shared__ float partial[2];

    float c = g_counts[g];
    float inv = (c > 0.0f) ? (1.0f / c) : 0.0f;
    #pragma unroll
    for (int i = j; i < D; i += 64) mean[i] = g_sums[g * D + i] * inv;
    __syncthreads();

    float h = b1[j];
    #pragma unroll 8
    for (int k = 0; k < D; ++k) h = fmaf(mean[k], W1[k * 64 + j], h);
    h = fmaxf(h, 0.0f);

    float p = h * W2[j];
    #pragma unroll
    for (int o = 16; o > 0; o >>= 1) p += __shfl_down_sync(WARP_FULL, p, o);
    if ((j & 31) == 0) partial[j >> 5] = p;
    __syncthreads();
    if (j == 0) out[g] = partial[0] + partial[1] + b2[0];
}

// ---------------------------------------------------------------------------
extern "C" void kernel_launch(void* const* d_in, const int* in_sizes, int n_in,
                              void* d_out, int out_size) {
    const float* x     = (const float*)d_in[0];
    const int*   batch = (const int*)d_in[1];
    const float* W1    = (const float*)d_in[2];
    const float* b1    = (const float*)d_in[3];
    const float* W2    = (const float*)d_in[4];
    const float* b2    = (const float*)d_in[5];
    float*       out   = (float*)d_out;

    const int N = in_sizes[1];  // number of rows (batch element count)

    // zero accumulators
    zero_kernel<<<(G * D + 255) / 256, 256>>>();

    // streaming segment-sum: 1184 blocks x 8 warps (2 CTAs/SM on 148 SMs)
    const int blocks = 1184;
    const int warps_total = blocks * 8;
    int rows_per_warp = (N + warps_total - 1) / warps_total;
    reduce_kernel<<<blocks, 256>>>((const float4*)x, batch, N, rows_per_warp);

    // MLP head
    mlp_kernel<<<G, 64>>>(W1, b1, W2, b2, out);
}

// round 10
// speedup vs baseline: 1.0264x; 1.0264x over previous
#include <cuda_runtime.h>
#include <cuda_bf16.h>

#define G 256
#define D 128
#define WARP_FULL 0xffffffffu

// Scratch accumulators (allocation-free rule: __device__ globals).
// Statically zero-initialized -> first call is correct; thereafter the MLP
// kernel's epilogue re-zeroes them so every graph replay starts clean.
__device__ float g_sums[G * D];
__device__ float g_counts[G];

// ---------------------------------------------------------------------------
// Kernel 1: streaming segment-sum.
// Each warp owns a contiguous chunk of rows. Lane L accumulates columns
// [4L, 4L+4) in a float4 register. batch is sorted, so we flush to global
// atomics only when the graph id changes (rare: ~G + #warps flushes total).
// Fast path: 32 rows at a time with a cooperative batch load + uniformity
// ballot -> fully unrolled 32 independent float4 loads (high MLP).
// ---------------------------------------------------------------------------
__device__ __forceinline__ void flush_seg(int g, int lane, const float4& acc, float cnt) {
    if (g < 0 || g >= G || cnt == 0.0f) return;   // clamp: never index OOB
    float* s = &g_sums[g * D + lane * 4];
    atomicAdd(s + 0, acc.x);
    atomicAdd(s + 1, acc.y);
    atomicAdd(s + 2, acc.z);
    atomicAdd(s + 3, acc.w);
    if (lane == 0) atomicAdd(&g_counts[g], cnt);
}

__global__ __launch_bounds__(256) void reduce_kernel(
    const float4* __restrict__ x4,      // [N, 32] float4 view of x[N,128]
    const int* __restrict__ batch,      // [N] int32
    int N, int rows_per_warp)
{
    const int warp_global = (blockIdx.x * blockDim.x + threadIdx.x) >> 5;
    const int lane = threadIdx.x & 31;

    int r0 = warp_global * rows_per_warp;
    if (r0 >= N) return;
    int r1 = min(N, r0 + rows_per_warp);

    float4 acc = make_float4(0.f, 0.f, 0.f, 0.f);
    float  cnt = 0.0f;
    int    cur_g = -1;

    int r = r0;
    while (r < r1) {
        int m = min(32, r1 - r);
        // cooperative batch load (inactive lanes replicate row r's value)
        int bi = batch[(lane < m) ? (r + lane) : r];
        int b0 = __shfl_sync(WARP_FULL, bi, 0);
        bool uni = __all_sync(WARP_FULL, bi == b0);

        if (uni && m == 32) {
            if (b0 != cur_g) {
                flush_seg(cur_g, lane, acc, cnt);
                acc = make_float4(0.f, 0.f, 0.f, 0.f);
                cnt = 0.0f;
                cur_g = b0;
            }
            const float4* p = x4 + (size_t)r * 32 + lane;
            #pragma unroll
            for (int i = 0; i < 32; ++i) {
                float4 v = __ldcs(p + (size_t)i * 32);   // streaming: no reuse
                acc.x += v.x; acc.y += v.y; acc.z += v.z; acc.w += v.w;
            }
            cnt += 32.0f;
            r += 32;
        } else {
            // slow path: per-row (segment boundary inside the 32-block, or tail)
            for (int i = 0; i < m; ++i) {
                int gi = __shfl_sync(WARP_FULL, bi, i);
                if (gi != cur_g) {
                    flush_seg(cur_g, lane, acc, cnt);
                    acc = make_float4(0.f, 0.f, 0.f, 0.f);
                    cnt = 0.0f;
                    cur_g = gi;
                }
                float4 v = __ldcs(&x4[(size_t)(r + i) * 32 + lane]);
                acc.x += v.x; acc.y += v.y; acc.z += v.z; acc.w += v.w;
                cnt += 1.0f;
            }
            r += m;
        }
    }
    flush_seg(cur_g, lane, acc, cnt);
}

// ---------------------------------------------------------------------------
// Kernel 2: per-graph mean + MLP head, then self-clean the accumulators so
// the next graph replay starts from zero (replaces the old zero_kernel).
// 256 blocks (one per graph) x 64 threads (one per hidden unit).
// ---------------------------------------------------------------------------
__global__ __launch_bounds__(64) void mlp_kernel(
    const float* __restrict__ W1,   // [128, 64] row-major
    const float* __restrict__ b1,   // [64]
    const float* __restrict__ W2,   // [64, 1]
    const float* __restrict__ b2,   // [1]
    float* __restrict__ out)        // [G, 1]
{
    const int g = blockIdx.x;
    const int j = threadIdx.x;   // hidden unit 0..63

    __shared__ float mean[D];
    __shared__ float partial[2];

    float c = g_counts[g];
    float inv = (c > 0.0f) ? (1.0f / c) : 0.0f;
    #pragma unroll
    for (int i = j; i < D; i += 64) mean[i] = g_sums[g * D + i] * inv;
    __syncthreads();

    // reads complete -> zero accumulators for the next replay (this block
    // exclusively owns graph g, so no cross-block hazard)
    #pragma unroll
    for (int i = j; i < D; i += 64) g_sums[g * D + i] = 0.0f;
    if (j == 0) g_counts[g] = 0.0f;

    float h = b1[j];
    #pragma unroll 8
    for (int k = 0; k < D; ++k) h = fmaf(mean[k], W1[k * 64 + j], h);
    h = fmaxf(h, 0.0f);

    float p = h * W2[j];
    #pragma unroll
    for (int o = 16; o > 0; o >>= 1) p += __shfl_down_sync(WARP_FULL, p, o);
    if ((j & 31) == 0) partial[j >> 5] = p;
    __syncthreads();
    if (j == 0) out[g] = partial[0] + partial[1] + b2[0];
}

// ---------------------------------------------------------------------------
extern "C" void kernel_launch(void* const* d_in, const int* in_sizes, int n_in,
                              void* d_out, int out_size) {
    const float* x     = (const float*)d_in[0];
    const int*   batch = (const int*)d_in[1];
    const float* W1    = (const float*)d_in[2];
    const float* b1    = (const float*)d_in[3];
    const float* W2    = (const float*)d_in[4];
    const float* b2    = (const float*)d_in[5];
    float*       out   = (float*)d_out;

    const int N = in_sizes[1];  // number of rows (batch element count)

    // streaming segment-sum: 1184 blocks x 8 warps (2 CTAs/SM on 148 SMs)
    const int blocks = 1184;
    const int warps_total = blocks * 8;
    int rows_per_warp = (N + warps_total - 1) / warps_total;
    reduce_kernel<<<blocks, 256>>>((const float4*)x, batch, N, rows_per_warp);

    // MLP head + accumulator re-zero (self-cleaning graph)
    mlp_kernel<<<G, 64>>>(W1, b1, W2, b2, out);
}

// round 11
// speedup vs baseline: 1.0463x; 1.0193x over previous
#include <cuda_runtime.h>
#include <cuda_bf16.h>

#define G 256
#define D 128
#define H 64            // hidden units
#define GPB 4           // graphs per MLP block
#define WARP_FULL 0xffffffffu

// Scratch accumulators (allocation-free rule: __device__ globals).
// Statically zero-initialized -> first call correct; MLP epilogue re-zeroes
// them so every graph replay starts clean.
__device__ float g_sums[G * D];
__device__ float g_counts[G];

// ---------------------------------------------------------------------------
// Kernel 1: streaming segment-sum (unchanged — at the LTS ceiling).
// Each warp owns a contiguous row chunk; lane L accumulates cols [4L,4L+4)
// in a float4 register; atomics only at (rare) segment boundaries.
// ---------------------------------------------------------------------------
__device__ __forceinline__ void flush_seg(int g, int lane, const float4& acc, float cnt) {
    if (g < 0 || g >= G || cnt == 0.0f) return;
    float* s = &g_sums[g * D + lane * 4];
    atomicAdd(s + 0, acc.x);
    atomicAdd(s + 1, acc.y);
    atomicAdd(s + 2, acc.z);
    atomicAdd(s + 3, acc.w);
    if (lane == 0) atomicAdd(&g_counts[g], cnt);
}

__global__ __launch_bounds__(256) void reduce_kernel(
    const float4* __restrict__ x4,      // [N, 32] float4 view of x[N,128]
    const int* __restrict__ batch,      // [N] int32
    int N, int rows_per_warp)
{
    const int warp_global = (blockIdx.x * blockDim.x + threadIdx.x) >> 5;
    const int lane = threadIdx.x & 31;

    int r0 = warp_global * rows_per_warp;
    if (r0 >= N) return;
    int r1 = min(N, r0 + rows_per_warp);

    float4 acc = make_float4(0.f, 0.f, 0.f, 0.f);
    float  cnt = 0.0f;
    int    cur_g = -1;

    int r = r0;
    while (r < r1) {
        int m = min(32, r1 - r);
        int bi = batch[(lane < m) ? (r + lane) : r];
        int b0 = __shfl_sync(WARP_FULL, bi, 0);
        bool uni = __all_sync(WARP_FULL, bi == b0);

        if (uni && m == 32) {
            if (b0 != cur_g) {
                flush_seg(cur_g, lane, acc, cnt);
                acc = make_float4(0.f, 0.f, 0.f, 0.f);
                cnt = 0.0f;
                cur_g = b0;
            }
            const float4* p = x4 + (size_t)r * 32 + lane;
            #pragma unroll
            for (int i = 0; i < 32; ++i) {
                float4 v = __ldcs(p + (size_t)i * 32);   // streaming: no reuse
                acc.x += v.x; acc.y += v.y; acc.z += v.z; acc.w += v.w;
            }
            cnt += 32.0f;
            r += 32;
        } else {
            for (int i = 0; i < m; ++i) {
                int gi = __shfl_sync(WARP_FULL, bi, i);
                if (gi != cur_g) {
                    flush_seg(cur_g, lane, acc, cnt);
                    acc = make_float4(0.f, 0.f, 0.f, 0.f);
                    cnt = 0.0f;
                    cur_g = gi;
                }
                float4 v = __ldcs(&x4[(size_t)(r + i) * 32 + lane]);
                acc.x += v.x; acc.y += v.y; acc.z += v.z; acc.w += v.w;
                cnt += 1.0f;
            }
            r += m;
        }
    }
    flush_seg(cur_g, lane, acc, cnt);
}

// ---------------------------------------------------------------------------
// Kernel 2: per-graph mean + MLP head. 64 blocks x 256 threads; each block
// handles GPB=4 graphs and stages W1 (32 KB) + the 4 means in shared memory,
// so the per-thread dot product runs entirely out of smem (latency-hidden by
// 8 warps/block). Epilogue self-cleans the accumulators for the next replay.
// ---------------------------------------------------------------------------
__global__ __launch_bounds__(256) void mlp_kernel(
    const float* __restrict__ W1,   // [128, 64] row-major
    const float* __restrict__ b1,   // [64]
    const float* __restrict__ W2,   // [64, 1]
    const float* __restrict__ b2,   // [1]
    float* __restrict__ out)        // [G, 1]
{
    __shared__ float W1s[D * H];        // 32 KB
    __shared__ float mean[GPB][D];      // 2 KB
    __shared__ float partial[GPB][2];

    const int tid = threadIdx.x;
    const int gl  = tid >> 6;           // graph-in-block 0..3
    const int j   = tid & 63;           // hidden unit 0..63
    const int g   = blockIdx.x * GPB + gl;

    // stage W1 cooperatively: 8192 floats = 2048 float4, 8 per thread
    {
        const float4* w4 = (const float4*)W1;
        float4* s4 = (float4*)W1s;
        #pragma unroll
        for (int i = 0; i < (D * H / 4) / 256; ++i)
            s4[tid + i * 256] = w4[tid + i * 256];
    }

    // stage mean for this block's graph (64 threads per graph, 2 elems each)
    {
        float c = g_counts[g];
        float inv = (c > 0.0f) ? (1.0f / c) : 0.0f;
        #pragma unroll
        for (int i = j; i < D; i += 64) mean[gl][i] = g_sums[g * D + i] * inv;
    }
    __syncthreads();

    // self-clean accumulators for next replay (block owns its 4 graphs)
    #pragma unroll
    for (int i = j; i < D; i += 64) g_sums[g * D + i] = 0.0f;
    if (j == 0) g_counts[g] = 0.0f;

    // hidden unit j for graph g: h = relu(b1[j] + sum_k mean[k] * W1[k][j])
    float h = b1[j];
    #pragma unroll 16
    for (int k = 0; k < D; ++k)
        h = fmaf(mean[gl][k], W1s[k * H + j], h);   // mean: broadcast, W1s: conflict-free
    h = fmaxf(h, 0.0f);

    // output: sum over 64 hidden units (2 warps per graph group)
    float p = h * W2[j];
    #pragma unroll
    for (int o = 16; o > 0; o >>= 1) p += __shfl_down_sync(WARP_FULL, p, o);
    if ((j & 31) == 0) partial[gl][j >> 5] = p;
    __syncthreads();
    if (j == 0) out[g] = partial[gl][0] + partial[gl][1] + b2[0];
}

// ---------------------------------------------------------------------------
extern "C" void kernel_launch(void* const* d_in, const int* in_sizes, int n_in,
                              void* d_out, int out_size) {
    const float* x     = (const float*)d_in[0];
    const int*   batch = (const int*)d_in[1];
    const float* W1    = (const float*)d_in[2];
    const float* b1    = (const float*)d_in[3];
    const float* W2    = (const float*)d_in[4];
    const float* b2    = (const float*)d_in[5];
    float*       out   = (float*)d_out;

    const int N = in_sizes[1];

    // streaming segment-sum: 1184 blocks x 8 warps (2 CTAs/SM on 148 SMs)
    const int blocks = 1184;
    const int warps_total = blocks * 8;
    int rows_per_warp = (N + warps_total - 1) / warps_total;
    reduce_kernel<<<blocks, 256>>>((const float4*)x, batch, N, rows_per_warp);

    // MLP head + accumulator re-zero (self-cleaning graph)
    mlp_kernel<<<G / GPB, 256>>>(W1, b1, W2, b2, out);
}

// round 13
// speedup vs baseline: 1.0557x; 1.0091x over previous
#include <cuda_runtime.h>
#include <cuda_bf16.h>

#define G 256
#define D 128
#define H 64
#define WARP_FULL 0xffffffffu

// Scratch accumulators (allocation-free rule: __device__ globals).
// Statically zero-initialized -> first call correct; MLP epilogue re-zeroes
// them so every graph replay starts clean.
__device__ float g_sums[G * D];
__device__ float g_counts[G];

// ---------------------------------------------------------------------------
// Kernel 1: streaming segment-sum.
// Each warp owns a contiguous row chunk (exact multiple of 32 rows), lane L
// accumulates cols [4L,4L+4) in a float4 register; atomics only at (rare)
// segment boundaries. Fast path: 32-row uniform block, fully unrolled.
// ---------------------------------------------------------------------------
__device__ __forceinline__ void flush_seg(int g, int lane, const float4& acc, float cnt) {
    if (g < 0 || g >= G || cnt == 0.0f) return;
    float* s = &g_sums[g * D + lane * 4];
    atomicAdd(s + 0, acc.x);
    atomicAdd(s + 1, acc.y);
    atomicAdd(s + 2, acc.z);
    atomicAdd(s + 3, acc.w);
    if (lane == 0) atomicAdd(&g_counts[g], cnt);
}

__global__ __launch_bounds__(256) void reduce_kernel(
    const float4* __restrict__ x4,      // [N, 32] float4 view of x[N,128]
    const int* __restrict__ batch,      // [N] int32
    int N, int rows_per_warp)
{
    const int warp_global = (blockIdx.x * blockDim.x + threadIdx.x) >> 5;
    const int lane = threadIdx.x & 31;

    int r0 = warp_global * rows_per_warp;
    if (r0 >= N) return;
    int r1 = min(N, r0 + rows_per_warp);

    float4 acc = make_float4(0.f, 0.f, 0.f, 0.f);
    float  cnt = 0.0f;
    int    cur_g = -1;

    int r = r0;
    while (r < r1) {
        int m = min(32, r1 - r);
        int bi = batch[(lane < m) ? (r + lane) : r];
        int b0 = __shfl_sync(WARP_FULL, bi, 0);
        bool uni = __all_sync(WARP_FULL, bi == b0);

        if (uni && m == 32) {
            if (b0 != cur_g) {
                flush_seg(cur_g, lane, acc, cnt);
                acc = make_float4(0.f, 0.f, 0.f, 0.f);
                cnt = 0.0f;
                cur_g = b0;
            }
            const float4* p = x4 + (size_t)r * 32 + lane;
            #pragma unroll
            for (int i = 0; i < 32; ++i) {
                float4 v = __ldcs(p + (size_t)i * 32);   // streaming: no reuse
                acc.x += v.x; acc.y += v.y; acc.z += v.z; acc.w += v.w;
            }
            cnt += 32.0f;
            r += 32;
        } else {
            // slow path: only at true segment boundaries (or final ragged tail)
            for (int i = 0; i < m; ++i) {
                int gi = __shfl_sync(WARP_FULL, bi, i);
                if (gi != cur_g) {
                    flush_seg(cur_g, lane, acc, cnt);
                    acc = make_float4(0.f, 0.f, 0.f, 0.f);
                    cnt = 0.0f;
                    cur_g = gi;
                }
                float4 v = __ldcs(&x4[(size_t)(r + i) * 32 + lane]);
                acc.x += v.x; acc.y += v.y; acc.z += v.z; acc.w += v.w;
                cnt += 1.0f;
            }
            r += m;
        }
    }
    flush_seg(cur_g, lane, acc, cnt);
}

// ---------------------------------------------------------------------------
// Kernel 2: per-graph mean + MLP head. 256 blocks (one graph each) x 256
// threads. W1 (32 KB) staged to smem cooperatively; k-dim split across 4
// thread groups so compute + staging latency is spread over 8 warps and all
// SMs. Epilogue self-cleans the accumulators for the next graph replay.
// ---------------------------------------------------------------------------
__global__ __launch_bounds__(256) void mlp_kernel(
    const float* __restrict__ W1,   // [128, 64] row-major
    const float* __restrict__ b1,   // [64]
    const float* __restrict__ W2,   // [64, 1]
    const float* __restrict__ b2,   // [1]
    float* __restrict__ out)        // [G, 1]
{
    __shared__ float W1s[D * H];        // 32 KB
    __shared__ float mean[D];
    __shared__ float part[4][H];
    __shared__ float partial[2];

    const int tid = threadIdx.x;
    const int j   = tid & 63;           // hidden unit
    const int s   = tid >> 6;           // k-slice 0..3
    const int g   = blockIdx.x;

    // stage W1: 2048 float4, 8 per thread
    {
        const float4* w4 = (const float4*)W1;
        float4* s4 = (float4*)W1s;
        #pragma unroll
        for (int i = 0; i < 8; ++i)
            s4[tid + i * 256] = __ldg(w4 + tid + i * 256);
    }
    // stage mean (128 threads)
    float c = g_counts[g];
    float inv = (c > 0.0f) ? (1.0f / c) : 0.0f;
    if (tid < D) mean[tid] = g_sums[g * D + tid] * inv;
    __syncthreads();

    // self-clean accumulators for next replay (block owns graph g)
    if (tid < D) g_sums[g * D + tid] = 0.0f;
    if (tid == 0) g_counts[g] = 0.0f;

    // partial dot: k in [32s, 32s+32)
    float h = 0.0f;
    #pragma unroll
    for (int k = 32 * s; k < 32 * s + 32; ++k)
        h = fmaf(mean[k], W1s[k * H + j], h);   // broadcast + conflict-free
    part[s][j] = h;
    __syncthreads();

    if (tid < H) {
        float hf = b1[tid] + part[0][tid] + part[1][tid] + part[2][tid] + part[3][tid];
        hf = fmaxf(hf, 0.0f);
        float p = hf * W2[tid];
        #pragma unroll
        for (int o = 16; o > 0; o >>= 1) p += __shfl_down_sync(WARP_FULL, p, o);
        if ((tid & 31) == 0) partial[tid >> 5] = p;
    }
    __syncthreads();
    if (tid == 0) out[g] = partial[0] + partial[1] + b2[0];
}

// ---------------------------------------------------------------------------
extern "C" void kernel_launch(void* const* d_in, const int* in_sizes, int n_in,
                              void* d_out, int out_size) {
    const float* x     = (const float*)d_in[0];
    const int*   batch = (const int*)d_in[1];
    const float* W1    = (const float*)d_in[2];
    const float* b1    = (const float*)d_in[3];
    const float* W2    = (const float*)d_in[4];
    const float* b2    = (const float*)d_in[5];
    float*       out   = (float*)d_out;

    const int N = in_sizes[1];

    // streaming segment-sum: 2368 blocks x 8 warps (4 CTAs/SM on 148 SMs).
    // rows_per_warp rounded UP to a multiple of 32 so warp chunks hit the
    // 32-row fast path exclusively (no per-warp ragged tails).
    const int blocks = 2368;
    const int warps_total = blocks * 8;
    int rpw = (N + warps_total - 1) / warps_total;
    rpw = (rpw + 31) & ~31;
    reduce_kernel<<<blocks, 256>>>((const float4*)x, batch, N, rpw);

    // MLP head + accumulator re-zero (self-cleaning graph)
    mlp_kernel<<<G, 256>>>(W1, b1, W2, b2, out);
}

// round 15
// speedup vs baseline: 1.0769x; 1.0201x over previous
#include <cuda_runtime.h>
#include <cuda_bf16.h>

#define G 256
#define D 128
#define H 64
#define GPB 2           // graphs per MLP block (128 blocks -> single wave)
#define WARP_FULL 0xffffffffu

// Scratch accumulators (allocation-free rule: __device__ globals).
// Statically zero-initialized -> first call correct; MLP epilogue re-zeroes
// them so every graph replay starts clean.
__device__ float g_sums[G * D];
__device__ float g_counts[G];

// ---------------------------------------------------------------------------
// Kernel 1: streaming segment-sum (unchanged — ~6.6 TB/s, near HBM ceiling).
// ---------------------------------------------------------------------------
__device__ __forceinline__ void flush_seg(int g, int lane, const float4& acc, float cnt) {
    if (g < 0 || g >= G || cnt == 0.0f) return;
    float* s = &g_sums[g * D + lane * 4];
    atomicAdd(s + 0, acc.x);
    atomicAdd(s + 1, acc.y);
    atomicAdd(s + 2, acc.z);
    atomicAdd(s + 3, acc.w);
    if (lane == 0) atomicAdd(&g_counts[g], cnt);
}

__global__ __launch_bounds__(256) void reduce_kernel(
    const float4* __restrict__ x4,      // [N, 32] float4 view of x[N,128]
    const int* __restrict__ batch,      // [N] int32
    int N, int rows_per_warp)
{
    const int warp_global = (blockIdx.x * blockDim.x + threadIdx.x) >> 5;
    const int lane = threadIdx.x & 31;

    int r0 = warp_global * rows_per_warp;
    if (r0 >= N) return;
    int r1 = min(N, r0 + rows_per_warp);

    float4 acc = make_float4(0.f, 0.f, 0.f, 0.f);
    float  cnt = 0.0f;
    int    cur_g = -1;

    int r = r0;
    while (r < r1) {
        int m = min(32, r1 - r);
        int bi = batch[(lane < m) ? (r + lane) : r];
        int b0 = __shfl_sync(WARP_FULL, bi, 0);
        bool uni = __all_sync(WARP_FULL, bi == b0);

        if (uni && m == 32) {
            if (b0 != cur_g) {
                flush_seg(cur_g, lane, acc, cnt);
                acc = make_float4(0.f, 0.f, 0.f, 0.f);
                cnt = 0.0f;
                cur_g = b0;
            }
            const float4* p = x4 + (size_t)r * 32 + lane;
            #pragma unroll
            for (int i = 0; i < 32; ++i) {
                float4 v = __ldcs(p + (size_t)i * 32);   // streaming: no reuse
                acc.x += v.x; acc.y += v.y; acc.z += v.z; acc.w += v.w;
            }
            cnt += 32.0f;
            r += 32;
        } else {
            for (int i = 0; i < m; ++i) {
                int gi = __shfl_sync(WARP_FULL, bi, i);
                if (gi != cur_g) {
                    flush_seg(cur_g, lane, acc, cnt);
                    acc = make_float4(0.f, 0.f, 0.f, 0.f);
                    cnt = 0.0f;
                    cur_g = gi;
                }
                float4 v = __ldcs(&x4[(size_t)(r + i) * 32 + lane]);
                acc.x += v.x; acc.y += v.y; acc.z += v.z; acc.w += v.w;
                cnt += 1.0f;
            }
            r += m;
        }
    }
    flush_seg(cur_g, lane, acc, cnt);
}

// ---------------------------------------------------------------------------
// Kernel 2: per-graph mean + MLP head, PDL-overlapped.
// 128 blocks x 256 threads, 2 graphs per block (single wave on 148 SMs).
// With programmatic dependent launch, the W1 smem staging (the dominant
// latency) runs BEFORE cudaGridDependencySynchronize(), i.e. concurrently
// with the reduce kernel's tail wave. Only the g_sums reads wait.
// Thread layout: gl = tid>>7 (graph 0/1), s = (tid>>6)&1 (k-slice), j = tid&63.
// Epilogue self-cleans the accumulators for the next graph replay.
// ---------------------------------------------------------------------------
__global__ __launch_bounds__(256) void mlp_kernel(
    const float* __restrict__ W1,   // [128, 64] row-major
    const float* __restrict__ b1,   // [64]
    const float* __restrict__ W2,   // [64, 1]
    const float* __restrict__ b2,   // [1]
    float* __restrict__ out)        // [G, 1]
{
    __shared__ float W1s[D * H];            // 32 KB
    __shared__ float mean[GPB][D];
    __shared__ float part[GPB][2][H];
    __shared__ float partial[GPB][2];

    const int tid = threadIdx.x;
    const int gl  = tid >> 7;               // graph-in-block 0..1
    const int s   = (tid >> 6) & 1;         // k-slice 0..1
    const int j   = tid & 63;               // hidden unit 0..63
    const int g   = blockIdx.x * GPB + gl;

    // ---- pre-dependency phase: stage weights (overlaps reduce tail) ----
    {
        const float4* w4 = (const float4*)W1;
        float4* s4 = (float4*)W1s;
        #pragma unroll
        for (int i = 0; i < 8; ++i)                    // 2048 float4 total
            s4[tid + i * 256] = __ldg(w4 + tid + i * 256);
    }
    float b1j = b1[j];
    float w2j = W2[j];

    // ---- wait for reduce kernel's writes to be visible ----
    cudaGridDependencySynchronize();

    // stage means: 256 threads cover 2 graphs x 128 dims
    {
        int gg = blockIdx.x * GPB + (tid >> 7);
        int d  = tid & 127;
        float c = g_counts[gg];
        float inv = (c > 0.0f) ? (1.0f / c) : 0.0f;
        mean[tid >> 7][d] = g_sums[gg * D + d] * inv;
        // self-clean for next replay (block owns its 2 graphs)
        g_sums[gg * D + d] = 0.0f;
        if (d == 0) g_counts[gg] = 0.0f;
    }
    __syncthreads();

    // partial dot: k in [64s, 64s+64)
    float h = 0.0f;
    #pragma unroll
    for (int k = 64 * s; k < 64 * s + 64; ++k)
        h = fmaf(mean[gl][k], W1s[k * H + j], h);      // broadcast + stride-1
    part[gl][s][j] = h;
    __syncthreads();

    // combine slices, relu, second layer (128 threads: gl' = tid>>6, j'=tid&63)
    if (tid < 128) {
        int gl2 = tid >> 6;
        int j2  = tid & 63;
        float hf = b1[j2] + part[gl2][0][j2] + part[gl2][1][j2];
        hf = fmaxf(hf, 0.0f);
        float p = hf * W2[j2];
        #pragma unroll
        for (int o = 16; o > 0; o >>= 1) p += __shfl_down_sync(WARP_FULL, p, o);
        if ((tid & 31) == 0) partial[gl2][(tid >> 5) & 1] = p;
    }
    __syncthreads();
    if (tid < GPB) out[blockIdx.x * GPB + tid] = partial[tid][0] + partial[tid][1] + b2[0];
    (void)b1j; (void)w2j;
}

// ---------------------------------------------------------------------------
extern "C" void kernel_launch(void* const* d_in, const int* in_sizes, int n_in,
                              void* d_out, int out_size) {
    const float* x     = (const float*)d_in[0];
    const int*   batch = (const int*)d_in[1];
    const float* W1    = (const float*)d_in[2];
    const float* b1    = (const float*)d_in[3];
    const float* W2    = (const float*)d_in[4];
    const float* b2    = (const float*)d_in[5];
    float*       out   = (float*)d_out;

    const int N = in_sizes[1];

    // streaming segment-sum: 2368 blocks x 8 warps (4 CTAs/SM on 148 SMs),
    // rows_per_warp a multiple of 32 -> warps hit the fast path exclusively.
    const int blocks = 2368;
    const int warps_total = blocks * 8;
    int rpw = (N + warps_total - 1) / warps_total;
    rpw = (rpw + 31) & ~31;
    reduce_kernel<<<blocks, 256>>>((const float4*)x, batch, N, rpw);

    // MLP head with programmatic dependent launch: weight staging overlaps
    // the reduce kernel's tail; gridDependencySynchronize gates g_sums reads.
    cudaLaunchConfig_t cfg = {};
    cfg.gridDim  = dim3(G / GPB, 1, 1);
    cfg.blockDim = dim3(256, 1, 1);
    cfg.dynamicSmemBytes = 0;
    cfg.stream = 0;
    cudaLaunchAttribute attrs[1];
    attrs[0].id = cudaLaunchAttributeProgrammaticStreamSerialization;
    attrs[0].val.programmaticStreamSerializationAllowed = 1;
    cfg.attrs = attrs;
    cfg.numAttrs = 1;
    cudaLaunchKernelEx(&cfg, mlp_kernel, W1, b1, W2, b2, out);
}